// round 2
// baseline (speedup 1.0000x reference)
#include <cuda_runtime.h>
#include <cuda_bf16.h>

#define N_NODES 50000
#define N_EDGES 800000
#define F_X 128
#define F_E 128
#define HIDDEN 512
#define F_OUT 128

// Scratch (static device globals -- no runtime allocation allowed)
__device__ float g_agg[N_NODES * F_E];     // 25.6 MB: summed received-edge features
__device__ float g_h[N_NODES * HIDDEN];    // 102.4 MB: hidden activations

// ---------------------------------------------------------------------------
// Zero the aggregation buffer
// ---------------------------------------------------------------------------
__global__ void zero_agg_kernel() {
    int i = blockIdx.x * blockDim.x + threadIdx.x;
    const int n4 = N_NODES * F_E / 4;
    float4* p = reinterpret_cast<float4*>(g_agg);
    if (i < n4) p[i] = make_float4(0.f, 0.f, 0.f, 0.f);
}

// ---------------------------------------------------------------------------
// Scatter-add: one warp per edge, one float4 per lane (128 floats per edge).
// Uses red.global.add.v4.f32 (sm_90+) -> 1 reduction op per 16 bytes.
// ---------------------------------------------------------------------------
__global__ void __launch_bounds__(256) scatter_edges_kernel(
    const float4* __restrict__ edge_attr,   // [N_EDGES][32] float4
    const int* __restrict__ receivers)      // [N_EDGES]
{
    int gt = blockIdx.x * blockDim.x + threadIdx.x;
    int edge = gt >> 5;
    int lane = gt & 31;
    if (edge >= N_EDGES) return;

    int r = __ldg(receivers + edge);                 // broadcast within warp
    float4 v = edge_attr[(size_t)edge * 32 + lane];  // coalesced 512B per edge

    float* dst = g_agg + (size_t)r * F_E + lane * 4; // 16B aligned
    asm volatile("red.global.add.v4.f32 [%0], {%1,%2,%3,%4};"
                 :: "l"(dst), "f"(v.x), "f"(v.y), "f"(v.z), "f"(v.w)
                 : "memory");
}

// ---------------------------------------------------------------------------
// Tiled fp32 GEMM: C = act(A @ B + bias)
//   BM=128, BN=64, BK=16, 256 threads, each thread computes 8x4.
// CONCAT=true : A = [g_agg | nodes] (K=256, both halves stride 128),
//               writes g_h with ReLU.
// CONCAT=false: A = g_h (K=HIDDEN), writes C (d_out), no ReLU.
// ---------------------------------------------------------------------------
template<bool CONCAT>
__global__ void __launch_bounds__(256) gemm_kernel(
    const float* __restrict__ Aalt,   // nodes (only used when CONCAT)
    const float* __restrict__ B,      // [K][N] row-major
    const float* __restrict__ bias,   // [N]
    float* __restrict__ Cout,         // output when !CONCAT
    int M, int K, int N)
{
    constexpr int BM = 128, BN = 64, BK = 16;
    __shared__ float As[BK][BM + 1];   // +1 pad: kills cross-k bank conflicts
    __shared__ float Bs[BK][BN];

    const int m0 = blockIdx.y * BM;
    const int n0 = blockIdx.x * BN;
    const int tid = threadIdx.x;
    const int tx = tid & 15;   // n dir (16 x 4 = 64)
    const int ty = tid >> 4;   // m dir (16 x 8 = 128)

    float acc[8][4];
    #pragma unroll
    for (int i = 0; i < 8; i++)
        #pragma unroll
        for (int j = 0; j < 4; j++) acc[i][j] = 0.f;

    for (int k0 = 0; k0 < K; k0 += BK) {
        // --- choose A source for this K tile ---
        const float* Aptr;
        int kofs, Astride;
        if (CONCAT) {
            if (k0 < F_E) { Aptr = g_agg; kofs = k0; }
            else          { Aptr = Aalt;  kofs = k0 - F_E; }
            Astride = 128;
        } else {
            Aptr = g_h; kofs = k0; Astride = K;
        }

        // --- load A tile (128x16 = 512 float4, 2 per thread), transposed ---
        #pragma unroll
        for (int it = 0; it < 2; it++) {
            int j = tid + it * 256;
            int row = j >> 2;            // 0..127
            int kq  = (j & 3) * 4;       // 0,4,8,12
            int gr  = m0 + row;
            float4 v = make_float4(0.f, 0.f, 0.f, 0.f);
            if (gr < M)
                v = *reinterpret_cast<const float4*>(
                        Aptr + (size_t)gr * Astride + kofs + kq);
            As[kq + 0][row] = v.x;
            As[kq + 1][row] = v.y;
            As[kq + 2][row] = v.z;
            As[kq + 3][row] = v.w;
        }

        // --- load B tile (16x64 = 256 float4, 1 per thread) ---
        {
            int row = tid >> 4;          // 0..15
            int nq  = (tid & 15) * 4;    // 0..60
            float4 v = *reinterpret_cast<const float4*>(
                           B + (size_t)(k0 + row) * N + n0 + nq);
            *reinterpret_cast<float4*>(&Bs[row][nq]) = v;
        }
        __syncthreads();

        // --- compute ---
        #pragma unroll
        for (int kk = 0; kk < BK; kk++) {
            float a[8], b[4];
            #pragma unroll
            for (int i = 0; i < 8; i++) a[i] = As[kk][ty * 8 + i];
            float4 bb = *reinterpret_cast<const float4*>(&Bs[kk][tx * 4]);
            b[0] = bb.x; b[1] = bb.y; b[2] = bb.z; b[3] = bb.w;
            #pragma unroll
            for (int i = 0; i < 8; i++)
                #pragma unroll
                for (int j = 0; j < 4; j++)
                    acc[i][j] = fmaf(a[i], b[j], acc[i][j]);
        }
        __syncthreads();
    }

    // --- epilogue: bias (+ReLU for layer 1), float4 stores ---
    float4 bv = *reinterpret_cast<const float4*>(bias + n0 + tx * 4);
    #pragma unroll
    for (int i = 0; i < 8; i++) {
        int gr = m0 + ty * 8 + i;
        if (gr >= M) continue;
        float4 o;
        o.x = acc[i][0] + bv.x;
        o.y = acc[i][1] + bv.y;
        o.z = acc[i][2] + bv.z;
        o.w = acc[i][3] + bv.w;
        if (CONCAT) {
            o.x = fmaxf(o.x, 0.f); o.y = fmaxf(o.y, 0.f);
            o.z = fmaxf(o.z, 0.f); o.w = fmaxf(o.w, 0.f);
        }
        float* dst = CONCAT ? (g_h + (size_t)gr * N + n0 + tx * 4)
                            : (Cout + (size_t)gr * N + n0 + tx * 4);
        *reinterpret_cast<float4*>(dst) = o;
    }
}

// ---------------------------------------------------------------------------
// Launch: zero -> scatter -> gemm1(concat+relu) -> gemm2
// Inputs (metadata order): nodes, edge_attr, senders, receivers, W1, b1, W2, b2
// ---------------------------------------------------------------------------
extern "C" void kernel_launch(void* const* d_in, const int* in_sizes, int n_in,
                              void* d_out, int out_size)
{
    const float* nodes     = (const float*)d_in[0];
    const float4* edge_attr = (const float4*)d_in[1];
    // d_in[2] = senders (unused by this model)
    const int*   receivers = (const int*)d_in[3];
    const float* W1        = (const float*)d_in[4];
    const float* b1        = (const float*)d_in[5];
    const float* W2        = (const float*)d_in[6];
    const float* b2        = (const float*)d_in[7];
    float* out = (float*)d_out;

    // 1) zero agg buffer (1.6M float4)
    zero_agg_kernel<<<(N_NODES * F_E / 4 + 255) / 256, 256>>>();

    // 2) scatter-add edges (1 warp/edge -> 100000 blocks of 256)
    {
        long long total = (long long)N_EDGES * 32;
        int blocks = (int)((total + 255) / 256);
        scatter_edges_kernel<<<blocks, 256>>>(edge_attr, receivers);
    }

    // 3) GEMM1: [agg|nodes] @ W1 + b1, ReLU -> g_h   (M=50000, K=256, N=512)
    {
        dim3 grid(HIDDEN / 64, (N_NODES + 127) / 128);
        gemm_kernel<true><<<grid, 256>>>(nodes, W1, b1, nullptr,
                                         N_NODES, F_E + F_X, HIDDEN);
    }

    // 4) GEMM2: g_h @ W2 + b2 -> out   (M=50000, K=512, N=128)
    {
        dim3 grid(F_OUT / 64, (N_NODES + 127) / 128);
        gemm_kernel<false><<<grid, 256>>>(nullptr, W2, b2, out,
                                          N_NODES, HIDDEN, F_OUT);
    }
}

// round 5
// speedup vs baseline: 1.7640x; 1.7640x over previous
#include <cuda_runtime.h>
#include <cstdint>

#define N_NODES 50000
#define N_EDGES 800000
#define F_X 128
#define F_E 128
#define HIDDEN 512
#define F_OUT 128

// ---------------- scratch (static device globals; no runtime alloc) --------
__device__ float    g_agg[(size_t)N_NODES * F_E];              // 25.6 MB
__device__ float    g_h[(size_t)N_NODES * HIDDEN];             // 102.4 MB
__device__ uint32_t g_W1t[(size_t)HIDDEN * (F_E + F_X)];       // W1^T tf32 [512][256]
__device__ uint32_t g_W2t[(size_t)F_OUT * HIDDEN];             // W2^T tf32 [128][512]

__device__ __forceinline__ uint32_t f2tf32(float f) {
    uint32_t r; asm("cvt.rna.tf32.f32 %0, %1;" : "=r"(r) : "f"(f)); return r;
}

// ---------------------------------------------------------------------------
// zero agg buffer
// ---------------------------------------------------------------------------
__global__ void zero_agg_kernel() {
    int i = blockIdx.x * blockDim.x + threadIdx.x;
    const int n4 = N_NODES * F_E / 4;
    float4* p = reinterpret_cast<float4*>(g_agg);
    if (i < n4) p[i] = make_float4(0.f, 0.f, 0.f, 0.f);
}

// ---------------------------------------------------------------------------
// scatter-add: one warp per edge, red.global.add.v4.f32
// ---------------------------------------------------------------------------
__global__ void __launch_bounds__(256) scatter_edges_kernel(
    const float4* __restrict__ edge_attr, const int* __restrict__ receivers)
{
    int gt = blockIdx.x * blockDim.x + threadIdx.x;
    int edge = gt >> 5;
    int lane = gt & 31;
    if (edge >= N_EDGES) return;

    int r = __ldg(receivers + edge);
    float4 v = edge_attr[(size_t)edge * 32 + lane];
    float* dst = g_agg + (size_t)r * F_E + lane * 4;
    asm volatile("red.global.add.v4.f32 [%0], {%1,%2,%3,%4};"
                 :: "l"(dst), "f"(v.x), "f"(v.y), "f"(v.z), "f"(v.w)
                 : "memory");
}

// ---------------------------------------------------------------------------
// W [K][N] row-major -> Wt [N][K] (tf32 bits, K contiguous = col-major B)
// ---------------------------------------------------------------------------
__global__ void transpose_tf32_kernel(const float* __restrict__ W,
                                      uint32_t* __restrict__ Wt, int K, int N)
{
    int idx = blockIdx.x * blockDim.x + threadIdx.x;
    if (idx >= K * N) return;
    int n = idx / K;
    int k = idx - n * K;
    Wt[idx] = f2tf32(W[(size_t)k * N + n]);
}

// ---------------------------------------------------------------------------
// tf32 mma.sync GEMM:  C = act(A @ Wt^T + bias)
//   BM=128, BN=128, BK=16.  256 threads = 8 warps (2m x 4n),
//   warp tile 64x32 = 4x4 m16n8k8 tiles.
// L1=true : A = [g_agg | nodes] (K=256), out = g_h, bias+ReLU, N=512
// L1=false: A = g_h (K=512), out = Cout, bias only, N=128
// ---------------------------------------------------------------------------
template <bool L1>
__global__ void __launch_bounds__(256)
gemm_mma_kernel(const float* __restrict__ nodes,
                const uint32_t* __restrict__ Wt,
                const float* __restrict__ bias,
                float* __restrict__ Cout)
{
    constexpr int K = L1 ? (F_E + F_X) : HIDDEN;
    constexpr int N = L1 ? HIDDEN : F_OUT;
    constexpr int M = N_NODES;
    constexpr int BK = 16;
    constexpr int LDS_PAD = 20;          // stride 20 floats: conflict-free frags

    __shared__ uint32_t As[128 * LDS_PAD];   // A tile, tf32 bits
    __shared__ uint32_t Bs[128 * LDS_PAD];   // B tile [n][k], tf32 bits

    const int tid  = threadIdx.x;
    const int lane = tid & 31;
    const int warp = tid >> 5;
    const int m0 = blockIdx.y * 128;
    const int n0 = blockIdx.x * 128;
    const int warp_m = (warp >> 2) * 64;     // 0 or 64
    const int warp_n = (warp & 3) * 32;      // 0,32,64,96
    const int g  = lane >> 2;                // 0..7
    const int t4 = lane & 3;                 // 0..3

    float acc[4][4][4];
    #pragma unroll
    for (int mt = 0; mt < 4; ++mt)
        #pragma unroll
        for (int nt = 0; nt < 4; ++nt)
            #pragma unroll
            for (int i = 0; i < 4; ++i) acc[mt][nt][i] = 0.f;

    for (int k0 = 0; k0 < K; k0 += BK) {
        // ---- choose A source for this K chunk (free concat) ----
        const float* Abase;
        int kofs, strideA;
        if (L1) {
            if (k0 < F_E) { Abase = g_agg; kofs = k0; }
            else          { Abase = nodes; kofs = k0 - F_E; }
            strideA = 128;
        } else {
            Abase = g_h; kofs = k0; strideA = K;
        }

        // ---- A tile: 128 rows x 16 k (512 float4; 2/thread), cvt->tf32 ----
        #pragma unroll
        for (int it = 0; it < 2; ++it) {
            int e = tid + it * 256;          // 0..511
            int row = e >> 2, q = e & 3;
            int gr = m0 + row;
            float4 v = make_float4(0.f, 0.f, 0.f, 0.f);
            if (gr < M)
                v = *reinterpret_cast<const float4*>(
                        Abase + (size_t)gr * strideA + kofs + q * 4);
            uint4 t;
            t.x = f2tf32(v.x); t.y = f2tf32(v.y);
            t.z = f2tf32(v.z); t.w = f2tf32(v.w);
            *reinterpret_cast<uint4*>(&As[row * LDS_PAD + q * 4]) = t;
        }
        // ---- B tile: 128 n-rows x 16 k from Wt (already tf32) ----
        #pragma unroll
        for (int it = 0; it < 2; ++it) {
            int e = tid + it * 256;
            int row = e >> 2, q = e & 3;
            uint4 t = *reinterpret_cast<const uint4*>(
                          Wt + (size_t)(n0 + row) * K + k0 + q * 4);
            *reinterpret_cast<uint4*>(&Bs[row * LDS_PAD + q * 4]) = t;
        }
        __syncthreads();

        // ---- compute: 2 k8-steps ----
        #pragma unroll
        for (int ks = 0; ks < 2; ++ks) {
            const int kb = ks * 8;
            uint32_t a[4][4];
            #pragma unroll
            for (int mt = 0; mt < 4; ++mt) {
                int mb = warp_m + mt * 16;
                a[mt][0] = As[(mb + g)     * LDS_PAD + kb + t4];
                a[mt][1] = As[(mb + g + 8) * LDS_PAD + kb + t4];
                a[mt][2] = As[(mb + g)     * LDS_PAD + kb + t4 + 4];
                a[mt][3] = As[(mb + g + 8) * LDS_PAD + kb + t4 + 4];
            }
            uint32_t b[4][2];
            #pragma unroll
            for (int nt = 0; nt < 4; ++nt) {
                int nb = warp_n + nt * 8;
                b[nt][0] = Bs[(nb + g) * LDS_PAD + kb + t4];
                b[nt][1] = Bs[(nb + g) * LDS_PAD + kb + t4 + 4];
            }
            #pragma unroll
            for (int mt = 0; mt < 4; ++mt)
                #pragma unroll
                for (int nt = 0; nt < 4; ++nt) {
                    asm volatile(
                        "mma.sync.aligned.m16n8k8.row.col.f32.tf32.tf32.f32 "
                        "{%0,%1,%2,%3}, {%4,%5,%6,%7}, {%8,%9}, {%0,%1,%2,%3};"
                        : "+f"(acc[mt][nt][0]), "+f"(acc[mt][nt][1]),
                          "+f"(acc[mt][nt][2]), "+f"(acc[mt][nt][3])
                        : "r"(a[mt][0]), "r"(a[mt][1]),
                          "r"(a[mt][2]), "r"(a[mt][3]),
                          "r"(b[nt][0]), "r"(b[nt][1]));
                }
        }
        __syncthreads();
    }

    // ---- epilogue: bias (+ReLU), float2 stores ----
    #pragma unroll
    for (int mt = 0; mt < 4; ++mt) {
        #pragma unroll
        for (int nt = 0; nt < 4; ++nt) {
            int gc = n0 + warp_n + nt * 8 + t4 * 2;
            float2 bv = *reinterpret_cast<const float2*>(bias + gc);
            #pragma unroll
            for (int h = 0; h < 2; ++h) {      // h=0: rows +0, h=1: rows +8
                int gr = m0 + warp_m + mt * 16 + g + h * 8;
                if (gr >= M) continue;
                float2 o;
                o.x = acc[mt][nt][h * 2 + 0] + bv.x;
                o.y = acc[mt][nt][h * 2 + 1] + bv.y;
                if (L1) { o.x = fmaxf(o.x, 0.f); o.y = fmaxf(o.y, 0.f); }
                float* dst = L1 ? (g_h + (size_t)gr * N + gc)
                                : (Cout + (size_t)gr * N + gc);
                *reinterpret_cast<float2*>(dst) = o;
            }
        }
    }
}

// ---------------------------------------------------------------------------
// launch: zero -> scatter -> transpose W1/W2 -> gemm1 -> gemm2
// Inputs: nodes, edge_attr, senders, receivers, W1, b1, W2, b2
// ---------------------------------------------------------------------------
extern "C" void kernel_launch(void* const* d_in, const int* in_sizes, int n_in,
                              void* d_out, int out_size)
{
    const float*  nodes     = (const float*)d_in[0];
    const float4* edge_attr = (const float4*)d_in[1];
    const int*    receivers = (const int*)d_in[3];
    const float*  W1        = (const float*)d_in[4];
    const float*  b1        = (const float*)d_in[5];
    const float*  W2        = (const float*)d_in[6];
    const float*  b2        = (const float*)d_in[7];
    float* out = (float*)d_out;

    uint32_t* w1t = nullptr; uint32_t* w2t = nullptr;
    cudaGetSymbolAddress((void**)&w1t, g_W1t);
    cudaGetSymbolAddress((void**)&w2t, g_W2t);

    zero_agg_kernel<<<(N_NODES * F_E / 4 + 255) / 256, 256>>>();

    {
        long long total = (long long)N_EDGES * 32;
        int blocks = (int)((total + 255) / 256);
        scatter_edges_kernel<<<blocks, 256>>>(edge_attr, receivers);
    }

    transpose_tf32_kernel<<<((F_E + F_X) * HIDDEN + 255) / 256, 256>>>(
        W1, w1t, F_E + F_X, HIDDEN);
    transpose_tf32_kernel<<<(HIDDEN * F_OUT + 255) / 256, 256>>>(
        W2, w2t, HIDDEN, F_OUT);

    {
        dim3 grid(HIDDEN / 128, (N_NODES + 127) / 128);   // (4, 391)
        gemm_mma_kernel<true><<<grid, 256>>>(nodes, w1t, b1, nullptr);
    }
    {
        dim3 grid(F_OUT / 128, (N_NODES + 127) / 128);    // (1, 391)
        gemm_mma_kernel<false><<<grid, 256>>>(nullptr, w2t, b2, out);
    }
}